// round 5
// baseline (speedup 1.0000x reference)
#include <cuda_runtime.h>

// Fixed problem shape
#define NPIX      102400            // B*H*W = 4*160*160
#define HW        25600             // H*W
#define NV        1024
#define OUT_ELEMS (NV * 2 * 32 * 32)

// Gaussian in bin coordinates: t = (x+1)*16 - 0.5, sigma_bins = 0.8
// log2-space coefficient: -0.5/(0.8^2) * log2(e)
#define CEXP   (-1.12710546f)
#define SKIPTH (5e-6f)

__device__ int g_sizes[NV];

// ---------------------------------------------------------------------------
// Kernel 1: zero output (16MB) + zero g_sizes. No cross-block ordering needed.
// ---------------------------------------------------------------------------
__global__ void zero_kernel(float4* __restrict__ out) {
    int t4 = blockIdx.x * 1024 + threadIdx.x;   // 512 blocks x 256 thr x 4
    float4 z = make_float4(0.f, 0.f, 0.f, 0.f);
#pragma unroll
    for (int k = 0; k < 4; k++) out[t4 + k * 256] = z;
    int i = blockIdx.x * blockDim.x + threadIdx.x;
    if (i < NV) g_sizes[i] = 0;
}

// ---------------------------------------------------------------------------
// Kernel 2: segment bincount (runs after zero kernel -> no race)
// ---------------------------------------------------------------------------
__global__ void count_kernel(const int* __restrict__ seg) {
    int n = blockIdx.x * blockDim.x + threadIdx.x;
    if (n < NPIX) atomicAdd(&g_sizes[seg[n]], 1);
}

// ---------------------------------------------------------------------------
// Predicated vector reduction: issue red.v4 only if gate > SKIPTH.
// ---------------------------------------------------------------------------
__device__ __forceinline__ void red4p(float gate, float* p,
                                      float a, float b, float c, float d) {
    asm volatile(
        "{\n\t"
        ".reg .pred pg;\n\t"
        "setp.gt.f32 pg, %0, %1;\n\t"
        "@pg red.global.add.v4.f32 [%2], {%3,%4,%5,%6};\n\t"
        "}"
        :: "f"(gate), "f"(SKIPTH), "l"(p), "f"(a), "f"(b), "f"(c), "f"(d)
        : "memory");
}

// ---------------------------------------------------------------------------
// Kernel 3: windowed Parzen scatter — ONE THREAD PER (pixel, pair).
// p-window: 6 bins (floor-2..floor+3), q-window: 12 bins 4-aligned,
// corner chunks with product weight < 5e-6 predicated off.
// Doubles warp parallelism vs per-pixel threads (occ 33% -> ~67%).
// ---------------------------------------------------------------------------
__global__ void __launch_bounds__(256)
hist_kernel(const int* __restrict__ seg,
            const int* __restrict__ byx,
            const float* __restrict__ grad,
            float* __restrict__ out) {
    int tid  = blockIdx.x * blockDim.x + threadIdx.x;
    int n    = tid >> 1;
    int pair = tid & 1;
    if (n >= NPIX) return;

    float tp, tq;
    if (pair == 0) {
        // coords: t = (x+1)*16 - 0.5 with x = byx*2/160 - 1
        tp = (float)byx[NPIX + n]     * 0.2f - 0.5f;
        tq = (float)byx[2 * NPIX + n] * 0.2f - 0.5f;
    } else {
        int b  = n / HW;
        int hw = n - b * HW;
        tp = grad[b * 2 * HW + hw]      * 16.f + 15.5f;
        tq = grad[b * 2 * HW + HW + hw] * 16.f + 15.5f;
        if (!(tp > -4.0f && tp < 35.0f && tq > -4.0f && tq < 35.0f)) return;
    }

    int v = seg[n];
    float inv = 1.0f / (float)__ldg(&g_sizes[v]);   // den = sizes * (P/32)^2 = sizes
    float* base = out + (size_t)v * 2048 + pair * 1024;

    int lo = min(26, max(0, __float2int_rd(tp) - 2));
    float wp[6];
#pragma unroll
    for (int k = 0; k < 6; k++) {
        float d = tp - (float)(lo + k);
        wp[k] = exp2f(CEXP * d * d);
    }
    int qa = min(20, max(0, (__float2int_rd(tq) - 3) & ~3));
    float wq[12];
#pragma unroll
    for (int k = 0; k < 12; k++) {
        float d = tq - (float)(qa + k);
        wq[k] = exp2f(CEXP * d * d);
    }
    float m0 = fmaxf(fmaxf(wq[0], wq[1]),  fmaxf(wq[2],  wq[3]));
    float m1 = fmaxf(fmaxf(wq[4], wq[5]),  fmaxf(wq[6],  wq[7]));
    float m2 = fmaxf(fmaxf(wq[8], wq[9]),  fmaxf(wq[10], wq[11]));

#pragma unroll
    for (int p = 0; p < 6; p++) {
        float wr = wp[p];
        float a  = wr * inv;
        float* row = base + (lo + p) * 32 + qa;
        red4p(wr * m0, row,     a * wq[0], a * wq[1], a * wq[2],  a * wq[3]);
        red4p(wr * m1, row + 4, a * wq[4], a * wq[5], a * wq[6],  a * wq[7]);
        red4p(wr * m2, row + 8, a * wq[8], a * wq[9], a * wq[10], a * wq[11]);
    }
}

// ---------------------------------------------------------------------------
extern "C" void kernel_launch(void* const* d_in, const int* in_sizes, int n_in,
                              void* d_out, int out_size) {
    const int*   seg  = (const int*)d_in[0];
    const int*   byx  = (const int*)d_in[1];
    const float* grad = (const float*)d_in[2];
    float*       out  = (float*)d_out;

    zero_kernel<<<512, 256>>>((float4*)out);
    count_kernel<<<(NPIX + 255) / 256, 256>>>(seg);
    hist_kernel<<<(2 * NPIX + 255) / 256, 256>>>(seg, byx, grad, out);
}